// round 1
// baseline (speedup 1.0000x reference)
#include <cuda_runtime.h>

// ---------------- problem constants ----------------
#define BB   2
#define VV   4
#define FD   128
#define ED   128
#define NHN  7
#define NN6  196608
#define NN5  49152
#define NN4  12288
#define PFN  32768
#define PP5  8192
#define PP4  2048
#define OO5  4
#define OO4  16

#define PPB    128            // fine points per block
#define NWARP  8              // warps per block (256 threads)

// Precomputed normalized interpolation weights (scratch; device globals allowed)
__device__ float g_w5[BB * PP5 * OO5 * NHN];   // [b][pc5][o5][n]
__device__ float g_w4[BB * PP4 * OO4 * NHN];   // [b][pc4][o4][n]

typedef unsigned long long u64;

__device__ __forceinline__ u64 pack2(float s) {
    u64 r; unsigned ui = __float_as_uint(s);
    asm("mov.b64 %0, {%1, %1};" : "=l"(r) : "r"(ui));
    return r;
}
__device__ __forceinline__ u64 fma2(u64 a, u64 b, u64 c) {
    u64 d;
    asm("fma.rn.f32x2 %0, %1, %2, %3;" : "=l"(d) : "l"(a), "l"(b), "l"(c));
    return d;
}

// ---------------- weights pre-pass ----------------
// One thread per (b, pc, o): normalize 1/(eps + rd + mask*BIG) over NH neighbors.
__global__ void weights_kernel(const float* __restrict__ rd5, const float* __restrict__ m5,
                               const float* __restrict__ rd4, const float* __restrict__ m4)
{
    const int T5 = BB * PP5 * OO5;   // 65536
    const int T4 = BB * PP4 * OO4;   // 65536
    int t = blockIdx.x * blockDim.x + threadIdx.x;
    if (t < T5) {
        int pcb = t / OO5;                        // b*P5 + pc
        const float* rd = rd5 + (size_t)t * NHN;
        const float* mm = m5 + (size_t)pcb * NHN;
        float w[NHN]; float s = 0.f;
#pragma unroll
        for (int n = 0; n < NHN; n++) { w[n] = 1.f / (1e-20f + rd[n] + mm[n] * 1e10f); s += w[n]; }
        float inv = 1.f / s;
#pragma unroll
        for (int n = 0; n < NHN; n++) g_w5[(size_t)t * NHN + n] = w[n] * inv;
    } else if (t < T5 + T4) {
        int tt = t - T5;
        int pcb = tt / OO4;                       // b*P4 + pc
        const float* rd = rd4 + (size_t)tt * NHN;
        const float* mm = m4 + (size_t)pcb * NHN;
        float w[NHN]; float s = 0.f;
#pragma unroll
        for (int n = 0; n < NHN; n++) { w[n] = 1.f / (1e-20f + rd[n] + mm[n] * 1e10f); s += w[n]; }
        float inv = 1.f / s;
#pragma unroll
        for (int n = 0; n < NHN; n++) g_w4[(size_t)tt * NHN + n] = w[n] * inv;
    }
}

// ---------------- fused main kernel ----------------
// Block: fixed (b,v), tile of PPB fine points. W (128x128) + bias in smem.
// Each warp processes 4 consecutive fine points at a time:
//  - gathered table6 rows staged in smem, GEMM via packed fp32x2 FMA
//  - level-5 interp: 4 points share coarse point -> each neighbor row loaded once
//  - level-4 interp: neighbor rows L1-cached across the 4 warps sharing pc4
__global__ __launch_bounds__(256)
void embed_kernel(const float* __restrict__ table6, const float* __restrict__ table5,
                  const float* __restrict__ table4, const float* __restrict__ Wm,
                  const float* __restrict__ bias,
                  const int* __restrict__ var_idx, const int* __restrict__ idx6,
                  const int* __restrict__ nh5, const int* __restrict__ nh4,
                  float* __restrict__ out)
{
    extern __shared__ float smem[];
    float* sW    = smem;               // FD*ED floats
    float* sBias = sW + FD * ED;       // 128 floats
    float* sA    = sBias + FD;         // NWARP*4*FD floats

    const int tid  = threadIdx.x;
    const int lane = tid & 31;
    const int wrp  = tid >> 5;

    const int tilesPerBV = PFN / PPB;            // 256
    const int bv   = blockIdx.x / tilesPerBV;
    const int tile = blockIdx.x % tilesPerBV;
    const int b = bv >> 2, v = bv & 3;
    const int vi = var_idx[b * VV + v];

    // stage W + bias
    for (int i = tid; i < FD * ED / 4; i += blockDim.x)
        ((float4*)sW)[i] = ((const float4*)Wm)[i];
    if (tid < FD / 4)
        ((float4*)sBias)[tid] = ((const float4*)bias)[tid];
    __syncthreads();

    const float* tb6 = table6 + (size_t)vi * ((size_t)NN6 * FD);
    const float* tb5 = table5 + (size_t)vi * ((size_t)NN5 * FD);
    const float* tb4 = table4 + (size_t)vi * ((size_t)NN4 * FD);

    const ulonglong2 bias2 = ((const ulonglong2*)sBias)[lane];
    float* sAw = sA + wrp * 4 * FD;

    for (int pass = 0; pass < PPB / (NWARP * 4); ++pass) {
        const int p0 = tile * PPB + pass * (NWARP * 4) + wrp * 4;   // aligned to 4
        const int* i6 = idx6 + b * PFN + p0;

        __syncwarp();   // previous pass finished reading sA
#pragma unroll
        for (int pt = 0; pt < 4; pt++) {
            int r = i6[pt];
            ((float4*)(sAw + pt * FD))[lane] =
                ((const float4*)(tb6 + (size_t)r * FD))[lane];
        }
        __syncwarp();

        u64 accL[4], accH[4];
#pragma unroll
        for (int pt = 0; pt < 4; pt++) { accL[pt] = bias2.x; accH[pt] = bias2.y; }

        // ---- GEMM: out[e] += sum_f A[f] * W[f][e], 4 points per warp ----
#pragma unroll 4
        for (int f = 0; f < FD; f += 4) {
            float4 a[4];
#pragma unroll
            for (int pt = 0; pt < 4; pt++)
                a[pt] = *(const float4*)(sAw + pt * FD + f);
#pragma unroll
            for (int ff = 0; ff < 4; ff++) {
                ulonglong2 wv = ((const ulonglong2*)(sW + (f + ff) * ED))[lane];
#pragma unroll
                for (int pt = 0; pt < 4; pt++) {
                    float as = (ff == 0) ? a[pt].x : (ff == 1) ? a[pt].y
                             : (ff == 2) ? a[pt].z : a[pt].w;
                    u64 ap = pack2(as);
                    accL[pt] = fma2(ap, wv.x, accL[pt]);
                    accH[pt] = fma2(ap, wv.y, accH[pt]);
                }
            }
        }

        // ---- level 5 interpolation (all 4 points share pc5) ----
        {
            const int pc5 = p0 >> 2;
            const int* np = nh5 + ((size_t)b * PP5 + pc5) * NHN;
            const float* wp = g_w5 + ((size_t)(b * PP5 + pc5)) * OO5 * NHN;  // [o=pt][n]
#pragma unroll
            for (int n = 0; n < NHN; n++) {
                int r = np[n];
                ulonglong2 t = ((const ulonglong2*)(tb5 + (size_t)r * FD))[lane];
#pragma unroll
                for (int pt = 0; pt < 4; pt++) {
                    u64 wn = pack2(wp[pt * NHN + n]);
                    accL[pt] = fma2(wn, t.x, accL[pt]);
                    accH[pt] = fma2(wn, t.y, accH[pt]);
                }
            }
        }
        // ---- level 4 interpolation (pc4 shared; o4 = (p0&15)+pt) ----
        {
            const int pc4 = p0 >> 4;
            const int o4  = p0 & 15;
            const int* np = nh4 + ((size_t)b * PP4 + pc4) * NHN;
            const float* wp = g_w4 + (((size_t)(b * PP4 + pc4)) * OO4 + o4) * NHN;
#pragma unroll
            for (int n = 0; n < NHN; n++) {
                int r = np[n];
                ulonglong2 t = ((const ulonglong2*)(tb4 + (size_t)r * FD))[lane];
#pragma unroll
                for (int pt = 0; pt < 4; pt++) {
                    u64 wn = pack2(wp[pt * NHN + n]);
                    accL[pt] = fma2(wn, t.x, accL[pt]);
                    accH[pt] = fma2(wn, t.y, accH[pt]);
                }
            }
        }

        // ---- store ----
#pragma unroll
        for (int pt = 0; pt < 4; pt++) {
            ulonglong2 o; o.x = accL[pt]; o.y = accH[pt];
            ((ulonglong2*)(out + ((size_t)bv * PFN + p0 + pt) * ED))[lane] = o;
        }
    }
}

// ---------------- launch ----------------
extern "C" void kernel_launch(void* const* d_in, const int* in_sizes, int n_in,
                              void* d_out, int out_size)
{
    const float* table6 = (const float*)d_in[0];
    const float* table5 = (const float*)d_in[1];
    const float* table4 = (const float*)d_in[2];
    const float* Wm     = (const float*)d_in[3];
    const float* bias   = (const float*)d_in[4];
    const float* rd5    = (const float*)d_in[5];
    const float* rd4    = (const float*)d_in[6];
    const float* m5     = (const float*)d_in[7];
    const float* m4     = (const float*)d_in[8];
    const int*   vidx   = (const int*)d_in[9];
    const int*   idx6   = (const int*)d_in[10];
    const int*   nh5    = (const int*)d_in[11];
    const int*   nh4    = (const int*)d_in[12];
    float* out = (float*)d_out;

    // weights pre-pass: 131072 threads
    {
        int total = BB * PP5 * OO5 + BB * PP4 * OO4;
        weights_kernel<<<(total + 255) / 256, 256>>>(rd5, m5, rd4, m4);
    }

    // main fused kernel
    {
        const int smemBytes = (FD * ED + FD + NWARP * 4 * FD) * (int)sizeof(float); // 82432
        cudaFuncSetAttribute(embed_kernel,
                             cudaFuncAttributeMaxDynamicSharedMemorySize, smemBytes);
        int grid = BB * VV * (PFN / PPB);   // 2048
        embed_kernel<<<grid, 256, smemBytes>>>(table6, table5, table4, Wm, bias,
                                               vidx, idx6, nh5, nh4, out);
    }
}

// round 3
// speedup vs baseline: 1.4131x; 1.4131x over previous
#include <cuda_runtime.h>
#include <cstdint>

// ---------------- problem constants ----------------
#define BB   2
#define VV   4
#define FD   128
#define ED   128
#define NHN  7
#define NN6  196608
#define NN5  49152
#define NN4  12288
#define PFN  32768
#define PP5  8192
#define PP4  2048
#define OO5  4
#define OO4  16

#define THREADS 512
#define NWARPS  16
#define TILE_M  128

#define APITCH  132                    // floats per smem row (pad: bank spread)
#define SMEM_A_FLOATS (TILE_M * APITCH)
#define SMEM_TOTAL (3 * SMEM_A_FLOATS * 4)   // A + Bt + Interp = 202752 B

typedef unsigned long long u64;

// Precomputed normalized interpolation weights
__device__ float g_w5[BB * PP5 * OO5 * NHN];
__device__ float g_w4[BB * PP4 * OO4 * NHN];

// ---------------- PTX helpers (baseline sm_80+ features only) ----------------
__device__ __forceinline__ uint32_t f2tf32(float f) {
    uint32_t r; asm("cvt.rna.tf32.f32 %0, %1;" : "=r"(r) : "f"(f)); return r;
}
__device__ __forceinline__ u64 pack2(float s) {
    u64 r; unsigned ui = __float_as_uint(s);
    asm("mov.b64 %0, {%1, %1};" : "=l"(r) : "r"(ui));
    return r;
}
__device__ __forceinline__ u64 fma2(u64 a, u64 b, u64 c) {
    u64 d; asm("fma.rn.f32x2 %0, %1, %2, %3;" : "=l"(d) : "l"(a), "l"(b), "l"(c)); return d;
}
__device__ __forceinline__ void mma_tf32(float* c, const uint32_t* a,
                                         uint32_t b0, uint32_t b1) {
    asm volatile(
        "mma.sync.aligned.m16n8k8.row.col.f32.tf32.tf32.f32 "
        "{%0,%1,%2,%3}, {%4,%5,%6,%7}, {%8,%9}, {%0,%1,%2,%3};"
        : "+f"(c[0]), "+f"(c[1]), "+f"(c[2]), "+f"(c[3])
        : "r"(a[0]), "r"(a[1]), "r"(a[2]), "r"(a[3]), "r"(b0), "r"(b1));
}

// ---------------- weights pre-pass ----------------
__global__ void weights_kernel(const float* __restrict__ rd5, const float* __restrict__ m5,
                               const float* __restrict__ rd4, const float* __restrict__ m4)
{
    const int T5 = BB * PP5 * OO5;
    const int T4 = BB * PP4 * OO4;
    int t = blockIdx.x * blockDim.x + threadIdx.x;
    if (t < T5) {
        int pcb = t / OO5;
        const float* rd = rd5 + (size_t)t * NHN;
        const float* mm = m5 + (size_t)pcb * NHN;
        float w[NHN]; float s = 0.f;
#pragma unroll
        for (int n = 0; n < NHN; n++) { w[n] = 1.f / (1e-20f + rd[n] + mm[n] * 1e10f); s += w[n]; }
        float inv = 1.f / s;
#pragma unroll
        for (int n = 0; n < NHN; n++) g_w5[(size_t)t * NHN + n] = w[n] * inv;
    } else if (t < T5 + T4) {
        int tt = t - T5;
        int pcb = tt / OO4;
        const float* rd = rd4 + (size_t)tt * NHN;
        const float* mm = m4 + (size_t)pcb * NHN;
        float w[NHN]; float s = 0.f;
#pragma unroll
        for (int n = 0; n < NHN; n++) { w[n] = 1.f / (1e-20f + rd[n] + mm[n] * 1e10f); s += w[n]; }
        float inv = 1.f / s;
#pragma unroll
        for (int n = 0; n < NHN; n++) g_w4[(size_t)tt * NHN + n] = w[n] * inv;
    }
}

// ---------------- fused mma.sync kernel ----------------
__global__ __launch_bounds__(THREADS, 1)
void embed_kernel(const float* __restrict__ table6, const float* __restrict__ table5,
                  const float* __restrict__ table4, const float* __restrict__ Wm,
                  const float* __restrict__ bias,
                  const int* __restrict__ var_idx, const int* __restrict__ idx6,
                  const int* __restrict__ nh5, const int* __restrict__ nh4,
                  float* __restrict__ out)
{
    extern __shared__ float smem[];
    float* sA = smem;                       // [128][132] tf32 bits of gathered table6
    float* sB = sA + SMEM_A_FLOATS;         // [128][132] tf32 bits of W^T (e-major)
    float* sI = sB + SMEM_A_FLOATS;         // [128][132] interp staging (fp32)

    const int tid  = threadIdx.x;
    const int lane = tid & 31;
    const int w    = tid >> 5;
    const int gid  = lane >> 2;             // 0..7
    const int tid4 = lane & 3;              // 0..3

    const int tilesPerBV = PFN / TILE_M;    // 256
    const int bv   = blockIdx.x / tilesPerBV;
    const int tile = blockIdx.x % tilesPerBV;
    const int b = bv >> 2, v = bv & 3;
    const int vi = var_idx[b * VV + v];

    const float* tb6 = table6 + (size_t)vi * ((size_t)NN6 * FD);
    const float* tb5 = table5 + (size_t)vi * ((size_t)NN5 * FD);
    const float* tb4 = table4 + (size_t)vi * ((size_t)NN4 * FD);

    // ---- stage A: gather 128 rows of table6, convert tf32 ----
    {
        const int* i6 = idx6 + b * PFN + tile * TILE_M;
#pragma unroll
        for (int j = 0; j < 8; j++) {
            int rl = w * 8 + j;
            int row = i6[rl];
            float4 a = ((const float4*)(tb6 + (size_t)row * FD))[lane];
            uint4 t;
            t.x = f2tf32(a.x); t.y = f2tf32(a.y); t.z = f2tf32(a.z); t.w = f2tf32(a.w);
            *(uint4*)(sA + rl * APITCH + lane * 4) = t;
        }
    }
    // ---- stage B = W^T (e-major): sB[e][f] = tf32(W[f][e]) ----
    for (int idx = tid; idx < FD * ED; idx += THREADS) {
        int f = idx >> 7, e = idx & 127;
        ((uint32_t*)sB)[e * APITCH + f] = f2tf32(Wm[idx]);
    }
    __syncthreads();

    // ---- register-tile GEMM: warp (mw, nw) computes 32x32 of C = A @ W ----
    const int mw = w & 3, nw = w >> 2;
    const int MR = mw * 32, NC = nw * 32;
    float acc[2][4][4];
#pragma unroll
    for (int mi = 0; mi < 2; mi++)
#pragma unroll
        for (int ni = 0; ni < 4; ni++)
#pragma unroll
            for (int r = 0; r < 4; r++) acc[mi][ni][r] = 0.f;

#pragma unroll
    for (int k0 = 0; k0 < FD; k0 += 8) {
        uint32_t af[2][4];
#pragma unroll
        for (int mi = 0; mi < 2; mi++) {
            const uint32_t* ap = (const uint32_t*)sA + (MR + mi * 16 + gid) * APITCH + k0 + tid4;
            af[mi][0] = ap[0];
            af[mi][2] = ap[4];
            af[mi][1] = ap[8 * APITCH];
            af[mi][3] = ap[8 * APITCH + 4];
        }
#pragma unroll
        for (int ni = 0; ni < 4; ni++) {
            const uint32_t* bp = (const uint32_t*)sB + (NC + ni * 8 + gid) * APITCH + k0 + tid4;
            uint32_t b0 = bp[0], b1 = bp[4];
            mma_tf32(acc[0][ni], af[0], b0, b1);
            mma_tf32(acc[1][ni], af[1], b0, b1);
        }
    }

    // ---- interpolation: bias + e5 + e4 -> sI ----
    {
        const ulonglong2 bias2 = ((const ulonglong2*)bias)[lane];
#pragma unroll
        for (int pass = 0; pass < 2; pass++) {
            const int pl0 = pass * 64 + w * 4;           // local point base (mult of 4)
            const int p0  = tile * TILE_M + pl0;
            u64 accL[4], accH[4];
#pragma unroll
            for (int pt = 0; pt < 4; pt++) { accL[pt] = bias2.x; accH[pt] = bias2.y; }

            // level 5: 4 points share pc5, o5 = pt
            {
                const int pc5 = p0 >> 2;
                const int* np = nh5 + ((size_t)b * PP5 + pc5) * NHN;
                const float* wp = g_w5 + ((size_t)(b * PP5 + pc5)) * OO5 * NHN;
#pragma unroll
                for (int n = 0; n < NHN; n++) {
                    int r = np[n];
                    ulonglong2 t = ((const ulonglong2*)(tb5 + (size_t)r * FD))[lane];
#pragma unroll
                    for (int pt = 0; pt < 4; pt++) {
                        u64 wn = pack2(wp[pt * NHN + n]);
                        accL[pt] = fma2(wn, t.x, accL[pt]);
                        accH[pt] = fma2(wn, t.y, accH[pt]);
                    }
                }
            }
            // level 4: pc4 shared, o4 = (p0&15)+pt
            {
                const int pc4 = p0 >> 4;
                const int o4  = p0 & 15;
                const int* np = nh4 + ((size_t)b * PP4 + pc4) * NHN;
                const float* wp = g_w4 + (((size_t)(b * PP4 + pc4)) * OO4 + o4) * NHN;
#pragma unroll
                for (int n = 0; n < NHN; n++) {
                    int r = np[n];
                    ulonglong2 t = ((const ulonglong2*)(tb4 + (size_t)r * FD))[lane];
#pragma unroll
                    for (int pt = 0; pt < 4; pt++) {
                        u64 wn = pack2(wp[pt * NHN + n]);
                        accL[pt] = fma2(wn, t.x, accL[pt]);
                        accH[pt] = fma2(wn, t.y, accH[pt]);
                    }
                }
            }
#pragma unroll
            for (int pt = 0; pt < 4; pt++) {
                ulonglong2 o; o.x = accL[pt]; o.y = accH[pt];
                *(ulonglong2*)(sI + (size_t)(pl0 + pt) * APITCH + lane * 4) = o;
            }
        }
    }
    __syncthreads();

    // ---- epilogue: C(regs) + interp(smem) -> gmem ----
    {
        float* ob = out + ((size_t)bv * PFN + (size_t)tile * TILE_M) * ED;
#pragma unroll
        for (int mi = 0; mi < 2; mi++) {
            const int row0 = MR + mi * 16 + gid;
            const int row1 = row0 + 8;
#pragma unroll
            for (int ni = 0; ni < 4; ni++) {
                const int col = NC + ni * 8 + 2 * tid4;
                float2 i0 = *(const float2*)(sI + (size_t)row0 * APITCH + col);
                float2 i1 = *(const float2*)(sI + (size_t)row1 * APITCH + col);
                float2 o0, o1;
                o0.x = acc[mi][ni][0] + i0.x;
                o0.y = acc[mi][ni][1] + i0.y;
                o1.x = acc[mi][ni][2] + i1.x;
                o1.y = acc[mi][ni][3] + i1.y;
                *(float2*)(ob + (size_t)row0 * ED + col) = o0;
                *(float2*)(ob + (size_t)row1 * ED + col) = o1;
            }
        }
    }
}

// ---------------- launch ----------------
extern "C" void kernel_launch(void* const* d_in, const int* in_sizes, int n_in,
                              void* d_out, int out_size)
{
    const float* table6 = (const float*)d_in[0];
    const float* table5 = (const float*)d_in[1];
    const float* table4 = (const float*)d_in[2];
    const float* Wm     = (const float*)d_in[3];
    const float* bias   = (const float*)d_in[4];
    const float* rd5    = (const float*)d_in[5];
    const float* rd4    = (const float*)d_in[6];
    const float* m5     = (const float*)d_in[7];
    const float* m4     = (const float*)d_in[8];
    const int*   vidx   = (const int*)d_in[9];
    const int*   idx6   = (const int*)d_in[10];
    const int*   nh5    = (const int*)d_in[11];
    const int*   nh4    = (const int*)d_in[12];
    float* out = (float*)d_out;

    {
        int total = BB * PP5 * OO5 + BB * PP4 * OO4;
        weights_kernel<<<(total + 255) / 256, 256>>>(rd5, m5, rd4, m4);
    }
    {
        cudaFuncSetAttribute(embed_kernel,
                             cudaFuncAttributeMaxDynamicSharedMemorySize, SMEM_TOTAL);
        int grid = BB * VV * (PFN / TILE_M);   // 2048
        embed_kernel<<<grid, THREADS, SMEM_TOTAL>>>(table6, table5, table4, Wm, bias,
                                                    vidx, idx6, nh5, nh4, out);
    }
}

// round 4
// speedup vs baseline: 1.9008x; 1.3451x over previous
#include <cuda_runtime.h>
#include <cstdint>

// ---------------- problem constants ----------------
#define BB   2
#define VV   4
#define FD   128
#define ED   128
#define NHN  7
#define NN6  196608
#define NN5  49152
#define NN4  12288
#define PFN  32768
#define PP5  8192
#define PP4  2048
#define OO5  4
#define OO4  16

#define THREADS 512
#define TILE_M  128

#define AP 132                       // sA pitch (floats): rows conflict-free
#define WP 136                       // sW pitch (floats): k-rows conflict-free
#define IP 132                       // sI pitch

#define SA_FLOATS (TILE_M * AP)      // 16896
#define SW_FLOATS (FD * WP)          // 17408
#define SI_FLOATS (TILE_M * IP)      // 16896
#define SMEM_TOTAL ((SA_FLOATS + SW_FLOATS + SI_FLOATS) * 4)   // 204800 B

typedef unsigned long long u64;

// Precomputed normalized interpolation weights
__device__ float g_w5[BB * PP5 * OO5 * NHN];
__device__ float g_w4[BB * PP4 * OO4 * NHN];

// ---------------- PTX helpers (baseline sm_80+ only) ----------------
__device__ __forceinline__ u64 pack2(float s) {
    u64 r; unsigned ui = __float_as_uint(s);
    asm("mov.b64 %0, {%1, %1};" : "=l"(r) : "r"(ui));
    return r;
}
__device__ __forceinline__ u64 fma2(u64 a, u64 b, u64 c) {
    u64 d; asm("fma.rn.f32x2 %0, %1, %2, %3;" : "=l"(d) : "l"(a), "l"(b), "l"(c)); return d;
}
__device__ __forceinline__ void mma_tf32(float* c, const uint32_t* a,
                                         uint32_t b0, uint32_t b1) {
    asm volatile(
        "mma.sync.aligned.m16n8k8.row.col.f32.tf32.tf32.f32 "
        "{%0,%1,%2,%3}, {%4,%5,%6,%7}, {%8,%9}, {%0,%1,%2,%3};"
        : "+f"(c[0]), "+f"(c[1]), "+f"(c[2]), "+f"(c[3])
        : "r"(a[0]), "r"(a[1]), "r"(a[2]), "r"(a[3]), "r"(b0), "r"(b1));
}
__device__ __forceinline__ void cp16(uint32_t dst, const void* src) {
    asm volatile("cp.async.cg.shared.global [%0], [%1], 16;" :: "r"(dst), "l"(src) : "memory");
}
#define CP_COMMIT() asm volatile("cp.async.commit_group;" ::: "memory")
#define CP_WAIT0()  asm volatile("cp.async.wait_group 0;" ::: "memory")

// ---------------- weights pre-pass ----------------
__global__ void weights_kernel(const float* __restrict__ rd5, const float* __restrict__ m5,
                               const float* __restrict__ rd4, const float* __restrict__ m4)
{
    const int T5 = BB * PP5 * OO5;
    const int T4 = BB * PP4 * OO4;
    int t = blockIdx.x * blockDim.x + threadIdx.x;
    if (t < T5) {
        int pcb = t / OO5;
        const float* rd = rd5 + (size_t)t * NHN;
        const float* mm = m5 + (size_t)pcb * NHN;
        float w[NHN]; float s = 0.f;
#pragma unroll
        for (int n = 0; n < NHN; n++) { w[n] = 1.f / (1e-20f + rd[n] + mm[n] * 1e10f); s += w[n]; }
        float inv = 1.f / s;
#pragma unroll
        for (int n = 0; n < NHN; n++) g_w5[(size_t)t * NHN + n] = w[n] * inv;
    } else if (t < T5 + T4) {
        int tt = t - T5;
        int pcb = tt / OO4;
        const float* rd = rd4 + (size_t)tt * NHN;
        const float* mm = m4 + (size_t)pcb * NHN;
        float w[NHN]; float s = 0.f;
#pragma unroll
        for (int n = 0; n < NHN; n++) { w[n] = 1.f / (1e-20f + rd[n] + mm[n] * 1e10f); s += w[n]; }
        float inv = 1.f / s;
#pragma unroll
        for (int n = 0; n < NHN; n++) g_w4[(size_t)tt * NHN + n] = w[n] * inv;
    }
}

// ---------------- fused kernel: cp.async staging || interp, then mma.sync ----------------
__global__ __launch_bounds__(THREADS, 1)
void embed_kernel(const float* __restrict__ table6, const float* __restrict__ table5,
                  const float* __restrict__ table4, const float* __restrict__ Wm,
                  const float* __restrict__ bias,
                  const int* __restrict__ var_idx, const int* __restrict__ idx6,
                  const int* __restrict__ nh5, const int* __restrict__ nh4,
                  float* __restrict__ out)
{
    extern __shared__ float smem[];
    float* sA = smem;                    // [128][132] gathered table6 rows (raw fp32)
    float* sW = sA + SA_FLOATS;          // [128][136] W row-major (raw fp32)
    float* sI = sW + SW_FLOATS;          // [128][132] interp staging

    const int tid  = threadIdx.x;
    const int lane = tid & 31;
    const int w    = tid >> 5;
    const int gid  = lane >> 2;          // 0..7
    const int tid4 = lane & 3;           // 0..3

    const int tilesPerBV = PFN / TILE_M; // 256
    const int bv   = blockIdx.x / tilesPerBV;
    const int tile = blockIdx.x % tilesPerBV;
    const int b = bv >> 2, v = bv & 3;
    const int vi = var_idx[b * VV + v];

    const float* tb6 = table6 + (size_t)vi * ((size_t)NN6 * FD);
    const float* tb5 = table5 + (size_t)vi * ((size_t)NN5 * FD);
    const float* tb4 = table4 + (size_t)vi * ((size_t)NN4 * FD);

    const uint32_t sA_u = (uint32_t)__cvta_generic_to_shared(sA);
    const uint32_t sW_u = (uint32_t)__cvta_generic_to_shared(sW);

    // ---- issue async staging: gathered A rows + W tile ----
    {
        const int* i6 = idx6 + b * PFN + tile * TILE_M;
#pragma unroll
        for (int j = 0; j < 8; j++) {
            int rl = w * 8 + j;
            int row = i6[rl];
            cp16(sA_u + (uint32_t)(rl * AP * 4 + lane * 16),
                 tb6 + (size_t)row * FD + lane * 4);
        }
#pragma unroll
        for (int i = 0; i < 8; i++) {
            int c = tid + i * 512;          // 4096 16B chunks
            int row = c >> 5, col = c & 31;
            cp16(sW_u + (uint32_t)(row * WP * 4 + col * 16),
                 Wm + (size_t)row * FD + col * 4);
        }
        CP_COMMIT();
    }

    // ---- interpolation overlaps the async copies: bias + e5 + e4 -> sI ----
    {
        const ulonglong2 bias2 = ((const ulonglong2*)bias)[lane];
#pragma unroll
        for (int pass = 0; pass < 2; pass++) {
            const int pl0 = pass * 64 + w * 4;       // local point base (mult of 4)
            const int p0  = tile * TILE_M + pl0;
            const int pc5 = p0 >> 2;
            const int pc4 = p0 >> 4;
            const int o4  = p0 & 15;

            const int* np5 = nh5 + ((size_t)b * PP5 + pc5) * NHN;
            const int* np4 = nh4 + ((size_t)b * PP4 + pc4) * NHN;
            const float* wp5 = g_w5 + ((size_t)(b * PP5 + pc5)) * OO5 * NHN;
            const float* wp4 = g_w4 + (((size_t)(b * PP4 + pc4)) * OO4 + o4) * NHN;

            int r5[NHN], r4[NHN];
#pragma unroll
            for (int n = 0; n < NHN; n++) { r5[n] = np5[n]; r4[n] = np4[n]; }

            ulonglong2 t5[NHN], t4[NHN];
#pragma unroll
            for (int n = 0; n < NHN; n++)
                t5[n] = ((const ulonglong2*)(tb5 + (size_t)r5[n] * FD))[lane];
#pragma unroll
            for (int n = 0; n < NHN; n++)
                t4[n] = ((const ulonglong2*)(tb4 + (size_t)r4[n] * FD))[lane];

            u64 accL[4], accH[4];
#pragma unroll
            for (int pt = 0; pt < 4; pt++) { accL[pt] = bias2.x; accH[pt] = bias2.y; }

#pragma unroll
            for (int n = 0; n < NHN; n++) {
#pragma unroll
                for (int pt = 0; pt < 4; pt++) {
                    u64 wn = pack2(wp5[pt * NHN + n]);
                    accL[pt] = fma2(wn, t5[n].x, accL[pt]);
                    accH[pt] = fma2(wn, t5[n].y, accH[pt]);
                }
            }
#pragma unroll
            for (int n = 0; n < NHN; n++) {
#pragma unroll
                for (int pt = 0; pt < 4; pt++) {
                    u64 wn = pack2(wp4[pt * NHN + n]);
                    accL[pt] = fma2(wn, t4[n].x, accL[pt]);
                    accH[pt] = fma2(wn, t4[n].y, accH[pt]);
                }
            }
#pragma unroll
            for (int pt = 0; pt < 4; pt++) {
                ulonglong2 o; o.x = accL[pt]; o.y = accH[pt];
                *(ulonglong2*)(sI + (size_t)(pl0 + pt) * IP + lane * 4) = o;
            }
        }
    }

    CP_WAIT0();
    __syncthreads();

    // ---- register-tile GEMM: warp (mw, nw) computes 32x32 of C = A @ W ----
    const int mw = w & 3, nw = w >> 2;
    const int MR = mw * 32, NC = nw * 32;
    float acc[2][4][4];
#pragma unroll
    for (int mi = 0; mi < 2; mi++)
#pragma unroll
        for (int ni = 0; ni < 4; ni++)
#pragma unroll
            for (int r = 0; r < 4; r++) acc[mi][ni][r] = 0.f;

#pragma unroll
    for (int k0 = 0; k0 < FD; k0 += 8) {
        uint32_t af[2][4];
#pragma unroll
        for (int mi = 0; mi < 2; mi++) {
            const uint32_t* ap = (const uint32_t*)sA + (MR + mi * 16 + gid) * AP + k0 + tid4;
            af[mi][0] = ap[0];
            af[mi][2] = ap[4];
            af[mi][1] = ap[8 * AP];
            af[mi][3] = ap[8 * AP + 4];
        }
#pragma unroll
        for (int ni = 0; ni < 4; ni++) {
            const uint32_t* bp = (const uint32_t*)sW + (k0 + tid4) * WP + NC + ni * 8 + gid;
            uint32_t b0 = bp[0], b1 = bp[4 * WP];
            mma_tf32(acc[0][ni], af[0], b0, b1);
            mma_tf32(acc[1][ni], af[1], b0, b1);
        }
    }

    // ---- epilogue: C(regs) + interp(smem) -> gmem ----
    {
        float* ob = out + ((size_t)bv * PFN + (size_t)tile * TILE_M) * ED;
#pragma unroll
        for (int mi = 0; mi < 2; mi++) {
            const int row0 = MR + mi * 16 + gid;
            const int row1 = row0 + 8;
#pragma unroll
            for (int ni = 0; ni < 4; ni++) {
                const int col = NC + ni * 8 + 2 * tid4;
                float2 i0 = *(const float2*)(sI + (size_t)row0 * IP + col);
                float2 i1 = *(const float2*)(sI + (size_t)row1 * IP + col);
                float2 o0, o1;
                o0.x = acc[mi][ni][0] + i0.x;
                o0.y = acc[mi][ni][1] + i0.y;
                o1.x = acc[mi][ni][2] + i1.x;
                o1.y = acc[mi][ni][3] + i1.y;
                *(float2*)(ob + (size_t)row0 * ED + col) = o0;
                *(float2*)(ob + (size_t)row1 * ED + col) = o1;
            }
        }
    }
}

// ---------------- launch ----------------
extern "C" void kernel_launch(void* const* d_in, const int* in_sizes, int n_in,
                              void* d_out, int out_size)
{
    const float* table6 = (const float*)d_in[0];
    const float* table5 = (const float*)d_in[1];
    const float* table4 = (const float*)d_in[2];
    const float* Wm     = (const float*)d_in[3];
    const float* bias   = (const float*)d_in[4];
    const float* rd5    = (const float*)d_in[5];
    const float* rd4    = (const float*)d_in[6];
    const float* m5     = (const float*)d_in[7];
    const float* m4     = (const float*)d_in[8];
    const int*   vidx   = (const int*)d_in[9];
    const int*   idx6   = (const int*)d_in[10];
    const int*   nh5    = (const int*)d_in[11];
    const int*   nh4    = (const int*)d_in[12];
    float* out = (float*)d_out;

    {
        int total = BB * PP5 * OO5 + BB * PP4 * OO4;
        weights_kernel<<<(total + 255) / 256, 256>>>(rd5, m5, rd4, m4);
    }
    {
        cudaFuncSetAttribute(embed_kernel,
                             cudaFuncAttributeMaxDynamicSharedMemorySize, SMEM_TOTAL);
        int grid = BB * VV * (PFN / TILE_M);   // 2048
        embed_kernel<<<grid, THREADS, SMEM_TOTAL>>>(table6, table5, table4, Wm, bias,
                                                    vidx, idx6, nh5, nh4, out);
    }
}

// round 5
// speedup vs baseline: 2.2128x; 1.1641x over previous
#include <cuda_runtime.h>
#include <cstdint>

// ---------------- problem constants ----------------
#define BB   2
#define VV   4
#define FD   128
#define ED   128
#define NHN  7
#define NN6  196608
#define NN5  49152
#define NN4  12288
#define PFN  32768
#define PP5  8192
#define PP4  2048
#define OO5  4
#define OO4  16

#define THREADS 256
#define TILE_M  64

#define AP 132                       // sA pitch (floats)
#define WP 136                       // sW pitch (floats)

#define SA_FLOATS (TILE_M * AP)      // 8448  (33.8 KB)
#define SW_FLOATS (FD * WP)          // 17408 (69.6 KB)
#define SMEM_TOTAL ((SA_FLOATS + SW_FLOATS) * 4)   // 103424 B -> 2 CTAs/SM

typedef unsigned long long u64;

// scratch (device globals allowed)
__device__ float g_w5[BB * PP5 * OO5 * NHN];
__device__ float g_w4[BB * PP4 * OO4 * NHN];
__device__ float g_Wc[FD * ED];      // W with rna tf32 rounding

// ---------------- PTX helpers (baseline sm_80+ only) ----------------
__device__ __forceinline__ uint32_t f2tf32(float f) {
    uint32_t r; asm("cvt.rna.tf32.f32 %0, %1;" : "=r"(r) : "f"(f)); return r;
}
__device__ __forceinline__ u64 pack2(float s) {
    u64 r; unsigned ui = __float_as_uint(s);
    asm("mov.b64 %0, {%1, %1};" : "=l"(r) : "r"(ui));
    return r;
}
__device__ __forceinline__ u64 fma2(u64 a, u64 b, u64 c) {
    u64 d; asm("fma.rn.f32x2 %0, %1, %2, %3;" : "=l"(d) : "l"(a), "l"(b), "l"(c)); return d;
}
__device__ __forceinline__ void mma_tf32(float* c, const uint32_t* a,
                                         uint32_t b0, uint32_t b1) {
    asm volatile(
        "mma.sync.aligned.m16n8k8.row.col.f32.tf32.tf32.f32 "
        "{%0,%1,%2,%3}, {%4,%5,%6,%7}, {%8,%9}, {%0,%1,%2,%3};"
        : "+f"(c[0]), "+f"(c[1]), "+f"(c[2]), "+f"(c[3])
        : "r"(a[0]), "r"(a[1]), "r"(a[2]), "r"(a[3]), "r"(b0), "r"(b1));
}
__device__ __forceinline__ void cp16(uint32_t dst, const void* src) {
    asm volatile("cp.async.cg.shared.global [%0], [%1], 16;" :: "r"(dst), "l"(src) : "memory");
}
#define CP_COMMIT() asm volatile("cp.async.commit_group;" ::: "memory")
#define CP_WAIT0()  asm volatile("cp.async.wait_group 0;" ::: "memory")

// ---------------- pre-pass: interp weights + W tf32(rna) copy ----------------
__global__ void weights_kernel(const float* __restrict__ rd5, const float* __restrict__ m5,
                               const float* __restrict__ rd4, const float* __restrict__ m4,
                               const float* __restrict__ Wm)
{
    const int T5 = BB * PP5 * OO5;            // 65536
    const int T4 = BB * PP4 * OO4;            // 65536
    int t = blockIdx.x * blockDim.x + threadIdx.x;
    if (t < T5) {
        int pcb = t / OO5;
        const float* rd = rd5 + (size_t)t * NHN;
        const float* mm = m5 + (size_t)pcb * NHN;
        float w[NHN]; float s = 0.f;
#pragma unroll
        for (int n = 0; n < NHN; n++) { w[n] = 1.f / (1e-20f + rd[n] + mm[n] * 1e10f); s += w[n]; }
        float inv = 1.f / s;
#pragma unroll
        for (int n = 0; n < NHN; n++) g_w5[(size_t)t * NHN + n] = w[n] * inv;
    } else if (t < T5 + T4) {
        int tt = t - T5;
        int pcb = tt / OO4;
        const float* rd = rd4 + (size_t)tt * NHN;
        const float* mm = m4 + (size_t)pcb * NHN;
        float w[NHN]; float s = 0.f;
#pragma unroll
        for (int n = 0; n < NHN; n++) { w[n] = 1.f / (1e-20f + rd[n] + mm[n] * 1e10f); s += w[n]; }
        float inv = 1.f / s;
#pragma unroll
        for (int n = 0; n < NHN; n++) g_w4[(size_t)tt * NHN + n] = w[n] * inv;
    } else if (t < T5 + T4 + FD * ED) {
        int i = t - (T5 + T4);
        ((uint32_t*)g_Wc)[i] = f2tf32(Wm[i]);
    }
}

// ---------------- fused kernel ----------------
__global__ __launch_bounds__(THREADS, 2)
void embed_kernel(const float* __restrict__ table6, const float* __restrict__ table5,
                  const float* __restrict__ table4,
                  const float* __restrict__ bias,
                  const int* __restrict__ var_idx, const int* __restrict__ idx6,
                  const int* __restrict__ nh5, const int* __restrict__ nh4,
                  float* __restrict__ out)
{
    extern __shared__ float smem[];
    float* sA = smem;                    // [64][132]: gathered A; later interp staging
    float* sW = sA + SA_FLOATS;          // [128][136]: W row-major (tf32-rna bits)

    const int tid  = threadIdx.x;
    const int lane = tid & 31;
    const int w    = tid >> 5;           // 0..7
    const int gid  = lane >> 2;
    const int tid4 = lane & 3;

    const int bv   = blockIdx.x >> 9;    // 512 tiles per (b,v)
    const int tile = blockIdx.x & 511;
    const int b = bv >> 2, v = bv & 3;
    const int vi = var_idx[b * VV + v];

    const float* tb6 = table6 + (size_t)vi * ((size_t)NN6 * FD);
    const float* tb5 = table5 + (size_t)vi * ((size_t)NN5 * FD);
    const float* tb4 = table4 + (size_t)vi * ((size_t)NN4 * FD);

    const uint32_t sA_u = (uint32_t)__cvta_generic_to_shared(sA);
    const uint32_t sW_u = (uint32_t)__cvta_generic_to_shared(sW);

    // ---- issue async staging: 64 gathered A rows + W tile ----
    {
        const int* i6 = idx6 + b * PFN + tile * TILE_M;
#pragma unroll
        for (int j = 0; j < 8; j++) {
            int rl = w * 8 + j;
            int row = i6[rl];
            cp16(sA_u + (uint32_t)(rl * AP * 4 + lane * 16),
                 tb6 + (size_t)row * FD + lane * 4);
        }
#pragma unroll
        for (int i = 0; i < 16; i++) {
            int c = tid + i * 256;            // 4096 16B chunks
            int row = c >> 5, col = c & 31;
            cp16(sW_u + (uint32_t)(row * WP * 4 + col * 16),
                 g_Wc + (size_t)row * FD + col * 4);
        }
        CP_COMMIT();
    }

    // ---- interpolation (overlaps copies): 8 points per warp, kept in regs ----
    u64 aL[8], aH[8];
    {
        const int pbase = tile * TILE_M + w * 8;      // multiple of 8
        const int pc5a = pbase >> 2;                  // two pc5 groups: pc5a, pc5a+1
        const int pc4  = pbase >> 4;                  // one pc4 group
        const int o4   = pbase & 15;

        const int* np5 = nh5 + ((size_t)b * PP5 + pc5a) * NHN;   // 14 ints (2 groups)
        const int* np4 = nh4 + ((size_t)b * PP4 + pc4) * NHN;
        const float* wp5 = g_w5 + ((size_t)(b * PP5 + pc5a)) * OO5 * NHN;
        const float* wp4 = g_w4 + (((size_t)(b * PP4 + pc4)) * OO4 + o4) * NHN;

        const ulonglong2 bias2 = ((const ulonglong2*)bias)[lane];
#pragma unroll
        for (int pt = 0; pt < 8; pt++) { aL[pt] = bias2.x; aH[pt] = bias2.y; }

        ulonglong2 t4[NHN], t5[NHN];
#pragma unroll
        for (int n = 0; n < NHN; n++)
            t4[n] = ((const ulonglong2*)(tb4 + (size_t)np4[n] * FD))[lane];
#pragma unroll
        for (int n = 0; n < NHN; n++)
            t5[n] = ((const ulonglong2*)(tb5 + (size_t)np5[n] * FD))[lane];

        // level-4: all 8 points share neighbor rows
#pragma unroll
        for (int n = 0; n < NHN; n++) {
#pragma unroll
            for (int pt = 0; pt < 8; pt++) {
                u64 wn = pack2(wp4[pt * NHN + n]);
                aL[pt] = fma2(wn, t4[n].x, aL[pt]);
                aH[pt] = fma2(wn, t4[n].y, aH[pt]);
            }
        }
        // level-5 group A: points 0..3
#pragma unroll
        for (int n = 0; n < NHN; n++) {
#pragma unroll
            for (int pt = 0; pt < 4; pt++) {
                u64 wn = pack2(wp5[pt * NHN + n]);
                aL[pt] = fma2(wn, t5[n].x, aL[pt]);
                aH[pt] = fma2(wn, t5[n].y, aH[pt]);
            }
        }
        // level-5 group B: points 4..7
#pragma unroll
        for (int n = 0; n < NHN; n++)
            t5[n] = ((const ulonglong2*)(tb5 + (size_t)np5[NHN + n] * FD))[lane];
#pragma unroll
        for (int n = 0; n < NHN; n++) {
#pragma unroll
            for (int pt = 0; pt < 4; pt++) {
                u64 wn = pack2(wp5[(OO5 + pt) * NHN + n]);
                aL[4 + pt] = fma2(wn, t5[n].x, aL[4 + pt]);
                aH[4 + pt] = fma2(wn, t5[n].y, aH[4 + pt]);
            }
        }
    }

    CP_WAIT0();
    __syncthreads();

    // ---- GEMM: warp (mw 0..1, nw 0..3) computes 32x32 of C = A @ W ----
    const int mw = w & 1, nw = w >> 1;
    const int MR = mw * 32, NC = nw * 32;
    float acc[2][4][4];
#pragma unroll
    for (int mi = 0; mi < 2; mi++)
#pragma unroll
        for (int ni = 0; ni < 4; ni++)
#pragma unroll
            for (int r = 0; r < 4; r++) acc[mi][ni][r] = 0.f;

#pragma unroll
    for (int k0 = 0; k0 < FD; k0 += 8) {
        uint32_t af[2][4];
#pragma unroll
        for (int mi = 0; mi < 2; mi++) {
            const uint32_t* ap = (const uint32_t*)sA + (MR + mi * 16 + gid) * AP + k0 + tid4;
            af[mi][0] = ap[0];
            af[mi][2] = ap[4];
            af[mi][1] = ap[8 * AP];
            af[mi][3] = ap[8 * AP + 4];
        }
#pragma unroll
        for (int ni = 0; ni < 4; ni++) {
            const uint32_t* bp = (const uint32_t*)sW + (k0 + tid4) * WP + NC + ni * 8 + gid;
            uint32_t b0 = bp[0], b1 = bp[4 * WP];
            mma_tf32(acc[0][ni], af[0], b0, b1);
            mma_tf32(acc[1][ni], af[1], b0, b1);
        }
    }
    __syncthreads();   // all A reads done; sA reusable

    // ---- stage interp regs into sA ----
#pragma unroll
    for (int pt = 0; pt < 8; pt++) {
        ulonglong2 o; o.x = aL[pt]; o.y = aH[pt];
        *(ulonglong2*)(sA + (size_t)(w * 8 + pt) * AP + lane * 4) = o;
    }
    __syncthreads();

    // ---- epilogue: C(regs) + interp(smem) -> gmem ----
    {
        float* ob = out + ((size_t)bv * PFN + (size_t)tile * TILE_M) * ED;
#pragma unroll
        for (int mi = 0; mi < 2; mi++) {
            const int row0 = MR + mi * 16 + gid;
            const int row1 = row0 + 8;
#pragma unroll
            for (int ni = 0; ni < 4; ni++) {
                const int col = NC + ni * 8 + 2 * tid4;
                float2 i0 = *(const float2*)(sA + (size_t)row0 * AP + col);
                float2 i1 = *(const float2*)(sA + (size_t)row1 * AP + col);
                float2 o0, o1;
                o0.x = acc[mi][ni][0] + i0.x;
                o0.y = acc[mi][ni][1] + i0.y;
                o1.x = acc[mi][ni][2] + i1.x;
                o1.y = acc[mi][ni][3] + i1.y;
                *(float2*)(ob + (size_t)row0 * ED + col) = o0;
                *(float2*)(ob + (size_t)row1 * ED + col) = o1;
            }
        }
    }
}

// ---------------- launch ----------------
extern "C" void kernel_launch(void* const* d_in, const int* in_sizes, int n_in,
                              void* d_out, int out_size)
{
    const float* table6 = (const float*)d_in[0];
    const float* table5 = (const float*)d_in[1];
    const float* table4 = (const float*)d_in[2];
    const float* Wm     = (const float*)d_in[3];
    const float* bias   = (const float*)d_in[4];
    const float* rd5    = (const float*)d_in[5];
    const float* rd4    = (const float*)d_in[6];
    const float* m5     = (const float*)d_in[7];
    const float* m4     = (const float*)d_in[8];
    const int*   vidx   = (const int*)d_in[9];
    const int*   idx6   = (const int*)d_in[10];
    const int*   nh5    = (const int*)d_in[11];
    const int*   nh4    = (const int*)d_in[12];
    float* out = (float*)d_out;

    {
        int total = BB * PP5 * OO5 + BB * PP4 * OO4 + FD * ED;
        weights_kernel<<<(total + 255) / 256, 256>>>(rd5, m5, rd4, m4, Wm);
    }
    {
        cudaFuncSetAttribute(embed_kernel,
                             cudaFuncAttributeMaxDynamicSharedMemorySize, SMEM_TOTAL);
        int grid = BB * VV * (PFN / TILE_M);   // 4096
        embed_kernel<<<grid, THREADS, SMEM_TOTAL>>>(table6, table5, table4, bias,
                                                    vidx, idx6, nh5, nh4, out);
    }
}